// round 1
// baseline (speedup 1.0000x reference)
#include <cuda_runtime.h>
#include <cuda_bf16.h>
#include <math.h>

// ---------------- problem constants ----------------
#define BATCH 4
#define TSEQ  1024
#define CDIM  768
#define NHEAD 12
#define HD    64
#define VOCAB 50304
#define NLAYER 12
#define NTOK  (BATCH*TSEQ)     // 4096
#define C3    (3*CDIM)         // 2304
#define C4    (4*CDIM)         // 3072

// ---------------- scratch (static device globals; no allocation allowed) ----
__device__ float g_h   [NTOK * CDIM];
__device__ float g_hn  [NTOK * CDIM];
__device__ float g_qkv [NTOK * C3];
__device__ float g_att [NTOK * CDIM];
__device__ float g_fc  [NTOK * C4];
__device__ float g_rowloss[NTOK];

// ---------------- embedding: h = wte[x] + wpe[t] ----------------
__global__ __launch_bounds__(256) void embed_kernel(const int* __restrict__ x,
                                                    const float* __restrict__ wte,
                                                    const float* __restrict__ wpe) {
    int m = blockIdx.x;              // token index 0..4095
    int t = m % TSEQ;
    int idx = x[m];
    const float* we = wte + (size_t)idx * CDIM;
    const float* wp = wpe + (size_t)t * CDIM;
    float* o = g_h + (size_t)m * CDIM;
    for (int c = threadIdx.x; c < CDIM; c += 256)
        o[c] = we[c] + wp[c];
}

// ---------------- layernorm (block per row) ----------------
__global__ __launch_bounds__(256) void ln_kernel(const float* __restrict__ in,
                                                 const float* __restrict__ w,
                                                 const float* __restrict__ bb,
                                                 float* __restrict__ out) {
    int row = blockIdx.x;
    const float* x = in + (size_t)row * CDIM;
    float s = 0.f, s2 = 0.f;
    for (int c = threadIdx.x; c < CDIM; c += 256) {
        float v = x[c]; s += v; s2 += v * v;
    }
    __shared__ float ss[8], ss2[8];
    #pragma unroll
    for (int o = 16; o; o >>= 1) {
        s  += __shfl_down_sync(0xffffffffu, s,  o);
        s2 += __shfl_down_sync(0xffffffffu, s2, o);
    }
    if ((threadIdx.x & 31) == 0) { ss[threadIdx.x >> 5] = s; ss2[threadIdx.x >> 5] = s2; }
    __syncthreads();
    if (threadIdx.x == 0) {
        float a = 0.f, a2 = 0.f;
        #pragma unroll
        for (int i = 0; i < 8; i++) { a += ss[i]; a2 += ss2[i]; }
        ss[0] = a; ss2[0] = a2;
    }
    __syncthreads();
    float mean = ss[0] * (1.f / CDIM);
    float var  = ss2[0] * (1.f / CDIM) - mean * mean;
    float rstd = rsqrtf(var + 1e-5f);
    float* o = out + (size_t)row * CDIM;
    for (int c = threadIdx.x; c < CDIM; c += 256)
        o[c] = (x[c] - mean) * rstd * w[c] + bb[c];
}

// ---------------- SGEMM: C = epi(A[M,K] @ op(B) + bias), optional residual ---
// EPI: 0 = none, 1 = gelu(tanh), 2 = add residual (add[m,n])
// TRANSB=false: B is [K,N] row-major. TRANSB=true: B is [N,K] row-major.
template<int EPI, bool TRANSB>
__global__ __launch_bounds__(256) void sgemm_k(const float* __restrict__ A,
                                               const float* __restrict__ B,
                                               const float* __restrict__ bias,
                                               const float* __restrict__ add,
                                               float* __restrict__ C,
                                               int M, int N, int K) {
    const int BM = 128, BN = 128, BK = 16, TM = 8, TN = 8;
    __shared__ float As[BK][BM];
    __shared__ float Bs[BK][BN];
    int tid = threadIdx.x;
    int tx = tid % 16, ty = tid / 16;
    int row0 = blockIdx.y * BM, col0 = blockIdx.x * BN;

    float acc[TM][TN];
    #pragma unroll
    for (int i = 0; i < TM; i++)
        #pragma unroll
        for (int j = 0; j < TN; j++) acc[i][j] = 0.f;

    for (int k0 = 0; k0 < K; k0 += BK) {
        // A tile: 128 rows x 16 k
        {
            int r = tid >> 2;
            int c = (tid & 3) * 4;
            #pragma unroll
            for (int i = 0; i < 2; i++) {
                float4 v = *(const float4*)(A + (size_t)(row0 + r + i * 64) * K + k0 + c);
                As[c + 0][r + i * 64] = v.x;
                As[c + 1][r + i * 64] = v.y;
                As[c + 2][r + i * 64] = v.z;
                As[c + 3][r + i * 64] = v.w;
            }
        }
        if (!TRANSB) {
            int r = tid >> 5;
            int c = (tid & 31) * 4;
            #pragma unroll
            for (int i = 0; i < 2; i++) {
                float4 v = *(const float4*)(B + (size_t)(k0 + r + i * 8) * N + col0 + c);
                *(float4*)&Bs[r + i * 8][c] = v;
            }
        } else {
            int n = tid >> 2;
            int c = (tid & 3) * 4;
            #pragma unroll
            for (int i = 0; i < 2; i++) {
                float4 v = *(const float4*)(B + (size_t)(col0 + n + i * 64) * K + k0 + c);
                Bs[c + 0][n + i * 64] = v.x;
                Bs[c + 1][n + i * 64] = v.y;
                Bs[c + 2][n + i * 64] = v.z;
                Bs[c + 3][n + i * 64] = v.w;
            }
        }
        __syncthreads();
        #pragma unroll
        for (int k = 0; k < BK; k++) {
            float ar[TM], br[TN];
            #pragma unroll
            for (int i = 0; i < TM; i++) ar[i] = As[k][ty * TM + i];
            #pragma unroll
            for (int j = 0; j < TN; j++) br[j] = Bs[k][tx * TN + j];
            #pragma unroll
            for (int i = 0; i < TM; i++)
                #pragma unroll
                for (int j = 0; j < TN; j++)
                    acc[i][j] += ar[i] * br[j];
        }
        __syncthreads();
    }

    #pragma unroll
    for (int i = 0; i < TM; i++) {
        int r = row0 + ty * TM + i;
        #pragma unroll
        for (int j = 0; j < TN; j++) {
            int cc = col0 + tx * TN + j;
            float v = acc[i][j];
            if (bias) v += bias[cc];
            if (EPI == 1) {
                float xx = v;
                float tt = 0.7978845608028654f * (xx + 0.044715f * xx * xx * xx);
                v = 0.5f * xx * (1.0f + tanhf(tt));
            } else if (EPI == 2) {
                v += add[(size_t)r * N + cc];
            }
            C[(size_t)r * N + cc] = v;
        }
    }
}

// ---------------- causal attention (flash-style, NO score scaling) ----------
// grid: (T/128, H, B); block: 128 threads; thread = one query row.
__global__ __launch_bounds__(128) void attn_kernel(const float* __restrict__ qkv,
                                                   float* __restrict__ att) {
    int b = blockIdx.z, h = blockIdx.y;
    int q0 = blockIdx.x * 128;
    int tid = threadIdx.x;
    int qi = q0 + tid;

    __shared__ float Ks[32][HD];
    __shared__ float Vs[32][HD];

    const size_t base = (size_t)b * TSEQ * C3;
    const float* qp = qkv + base + (size_t)qi * C3 + h * HD;
    float q[HD];
    #pragma unroll
    for (int d = 0; d < HD; d++) q[d] = qp[d];

    float m = -1e30f, l = 0.f;
    float acc[HD];
    #pragma unroll
    for (int d = 0; d < HD; d++) acc[d] = 0.f;

    int kend = q0 + 128;  // exclusive; multiple of 32
    for (int kj0 = 0; kj0 < kend; kj0 += 32) {
        __syncthreads();
        {   // cooperative load of 32 K rows and 32 V rows (64 floats each)
            int jj = tid >> 2;
            int f0 = (tid & 3) * 4;   // float4 slot base (16 slots per row)
            const float* kp = qkv + base + (size_t)(kj0 + jj) * C3 + CDIM + h * HD;
            const float* vp = kp + CDIM;
            #pragma unroll
            for (int i = 0; i < 4; i++) {
                ((float4*)Ks[jj])[f0 + i] = ((const float4*)kp)[f0 + i];
                ((float4*)Vs[jj])[f0 + i] = ((const float4*)vp)[f0 + i];
            }
        }
        __syncthreads();
        int jlim = qi - kj0; if (jlim > 31) jlim = 31;
        for (int jj = 0; jj <= jlim; jj++) {
            float s = 0.f;
            #pragma unroll
            for (int d = 0; d < HD; d++) s += q[d] * Ks[jj][d];
            float nm = fmaxf(m, s);
            float corr = __expf(m - nm);
            float p = __expf(s - nm);
            l = l * corr + p;
            #pragma unroll
            for (int d = 0; d < HD; d++) acc[d] = acc[d] * corr + p * Vs[jj][d];
            m = nm;
        }
    }
    float inv = 1.f / l;
    float* o = att + (size_t)(b * TSEQ + qi) * CDIM + h * HD;
    #pragma unroll
    for (int d = 0; d < HD; d++) o[d] = acc[d] * inv;
}

// ---------------- per-row cross-entropy ----------------
__global__ __launch_bounds__(256) void loss_row_kernel(const float* __restrict__ logits,
                                                       const int* __restrict__ targets) {
    int row = blockIdx.x;
    const float* x = logits + (size_t)row * VOCAB;
    __shared__ float sh[8];
    float mx = -1e30f;
    for (int c = threadIdx.x; c < VOCAB; c += 256) mx = fmaxf(mx, x[c]);
    #pragma unroll
    for (int o = 16; o; o >>= 1) mx = fmaxf(mx, __shfl_down_sync(0xffffffffu, mx, o));
    if ((threadIdx.x & 31) == 0) sh[threadIdx.x >> 5] = mx;
    __syncthreads();
    if (threadIdx.x == 0) {
        float a = sh[0];
        #pragma unroll
        for (int i = 1; i < 8; i++) a = fmaxf(a, sh[i]);
        sh[0] = a;
    }
    __syncthreads();
    mx = sh[0];
    __syncthreads();
    float s = 0.f;
    for (int c = threadIdx.x; c < VOCAB; c += 256) s += expf(x[c] - mx);
    #pragma unroll
    for (int o = 16; o; o >>= 1) s += __shfl_down_sync(0xffffffffu, s, o);
    if ((threadIdx.x & 31) == 0) sh[threadIdx.x >> 5] = s;
    __syncthreads();
    if (threadIdx.x == 0) {
        float a = 0.f;
        #pragma unroll
        for (int i = 0; i < 8; i++) a += sh[i];
        g_rowloss[row] = (mx + logf(a)) - x[targets[row]];
    }
}

__global__ __launch_bounds__(1024) void loss_reduce_kernel(float* __restrict__ out) {
    __shared__ float sh[1024];
    int t = threadIdx.x;
    float s = 0.f;
    for (int i = t; i < NTOK; i += 1024) s += g_rowloss[i];
    sh[t] = s;
    __syncthreads();
    for (int o = 512; o; o >>= 1) {
        if (t < o) sh[t] += sh[t + o];
        __syncthreads();
    }
    if (t == 0) out[0] = sh[0] * (1.f / NTOK);
}

// ---------------- launch ----------------
extern "C" void kernel_launch(void* const* d_in, const int* in_sizes, int n_in,
                              void* d_out, int out_size) {
    const int*   x       = (const int*)  d_in[0];
    const int*   targets = (const int*)  d_in[1];
    const float* wte     = (const float*)d_in[2];
    const float* wpe     = (const float*)d_in[3];
    const float* ln1_w   = (const float*)d_in[4];
    const float* ln1_b   = (const float*)d_in[5];
    const float* attn_w  = (const float*)d_in[6];
    const float* attn_b  = (const float*)d_in[7];
    const float* proj_w  = (const float*)d_in[8];
    const float* proj_b  = (const float*)d_in[9];
    const float* ln2_w   = (const float*)d_in[10];
    const float* ln2_b   = (const float*)d_in[11];
    const float* fc_w    = (const float*)d_in[12];
    const float* fc_b    = (const float*)d_in[13];
    const float* fc2_w   = (const float*)d_in[14];
    const float* fc2_b   = (const float*)d_in[15];
    const float* lnf_w   = (const float*)d_in[16];
    const float* lnf_b   = (const float*)d_in[17];

    float* logits = (float*)d_out;
    float* lossp  = (float*)d_out + (out_size - 1);

    float *p_h, *p_hn, *p_qkv, *p_att, *p_fc;
    cudaGetSymbolAddress((void**)&p_h,   g_h);
    cudaGetSymbolAddress((void**)&p_hn,  g_hn);
    cudaGetSymbolAddress((void**)&p_qkv, g_qkv);
    cudaGetSymbolAddress((void**)&p_att, g_att);
    cudaGetSymbolAddress((void**)&p_fc,  g_fc);

    embed_kernel<<<NTOK, 256>>>(x, wte, wpe);

    for (int l = 0; l < NLAYER; l++) {
        ln_kernel<<<NTOK, 256>>>(p_h, ln1_w + (size_t)l * CDIM, ln1_b + (size_t)l * CDIM, p_hn);
        sgemm_k<0, false><<<dim3(C3 / 128, NTOK / 128), 256>>>(
            p_hn, attn_w + (size_t)l * CDIM * C3, attn_b + (size_t)l * C3,
            nullptr, p_qkv, NTOK, C3, CDIM);
        attn_kernel<<<dim3(TSEQ / 128, NHEAD, BATCH), 128>>>(p_qkv, p_att);
        sgemm_k<2, false><<<dim3(CDIM / 128, NTOK / 128), 256>>>(
            p_att, proj_w + (size_t)l * CDIM * CDIM, proj_b + (size_t)l * CDIM,
            p_h, p_h, NTOK, CDIM, CDIM);
        ln_kernel<<<NTOK, 256>>>(p_h, ln2_w + (size_t)l * CDIM, ln2_b + (size_t)l * CDIM, p_hn);
        sgemm_k<1, false><<<dim3(C4 / 128, NTOK / 128), 256>>>(
            p_hn, fc_w + (size_t)l * CDIM * C4, fc_b + (size_t)l * C4,
            nullptr, p_fc, NTOK, C4, CDIM);
        sgemm_k<2, false><<<dim3(CDIM / 128, NTOK / 128), 256>>>(
            p_fc, fc2_w + (size_t)l * C4 * CDIM, fc2_b + (size_t)l * CDIM,
            p_h, p_h, NTOK, CDIM, C4);
    }

    ln_kernel<<<NTOK, 256>>>(p_h, lnf_w, lnf_b, p_hn);
    sgemm_k<0, true><<<dim3(VOCAB / 128, NTOK / 128), 256>>>(
        p_hn, wte, nullptr, nullptr, logits, NTOK, VOCAB, CDIM);

    loss_row_kernel<<<NTOK, 256>>>(logits, targets);
    loss_reduce_kernel<<<1, 1024>>>(lossp);
}

// round 5
// speedup vs baseline: 1.3585x; 1.3585x over previous
#include <cuda_runtime.h>
#include <cuda_bf16.h>
#include <math.h>
#include <stdint.h>

// ---------------- problem constants ----------------
#define BATCH 4
#define TSEQ  1024
#define CDIM  768
#define NHEAD 12
#define HD    64
#define VOCAB 50304
#define NLAYER 12
#define NTOK  (BATCH*TSEQ)     // 4096
#define C3    (3*CDIM)         // 2304
#define C4    (4*CDIM)         // 3072

// ---------------- scratch (static device globals; no allocation allowed) ----
__device__ float g_h   [NTOK * CDIM];
__device__ float g_hn  [NTOK * CDIM];
__device__ float g_qkv [NTOK * C3];
__device__ float g_att [NTOK * CDIM];
__device__ float g_fc  [NTOK * C4];
__device__ float g_rowloss[NTOK];

// ---------------- embedding: h = wte[x] + wpe[t] ----------------
__global__ __launch_bounds__(256) void embed_kernel(const int* __restrict__ x,
                                                    const float* __restrict__ wte,
                                                    const float* __restrict__ wpe) {
    int m = blockIdx.x;
    int t = m % TSEQ;
    int idx = x[m];
    const float* we = wte + (size_t)idx * CDIM;
    const float* wp = wpe + (size_t)t * CDIM;
    float* o = g_h + (size_t)m * CDIM;
    for (int c = threadIdx.x; c < CDIM; c += 256)
        o[c] = we[c] + wp[c];
}

// ---------------- layernorm (block per row) ----------------
__global__ __launch_bounds__(256) void ln_kernel(const float* __restrict__ in,
                                                 const float* __restrict__ w,
                                                 const float* __restrict__ bb,
                                                 float* __restrict__ out) {
    int row = blockIdx.x;
    const float* x = in + (size_t)row * CDIM;
    float s = 0.f, s2 = 0.f;
    for (int c = threadIdx.x; c < CDIM; c += 256) {
        float v = x[c]; s += v; s2 += v * v;
    }
    __shared__ float ss[8], ss2[8];
    #pragma unroll
    for (int o = 16; o; o >>= 1) {
        s  += __shfl_down_sync(0xffffffffu, s,  o);
        s2 += __shfl_down_sync(0xffffffffu, s2, o);
    }
    if ((threadIdx.x & 31) == 0) { ss[threadIdx.x >> 5] = s; ss2[threadIdx.x >> 5] = s2; }
    __syncthreads();
    if (threadIdx.x == 0) {
        float a = 0.f, a2 = 0.f;
        #pragma unroll
        for (int i = 0; i < 8; i++) { a += ss[i]; a2 += ss2[i]; }
        ss[0] = a; ss2[0] = a2;
    }
    __syncthreads();
    float mean = ss[0] * (1.f / CDIM);
    float var  = ss2[0] * (1.f / CDIM) - mean * mean;
    float rstd = rsqrtf(var + 1e-5f);
    float* o = out + (size_t)row * CDIM;
    for (int c = threadIdx.x; c < CDIM; c += 256)
        o[c] = (x[c] - mean) * rstd * w[c] + bb[c];
}

// ---------------- tf32 helpers ----------------
__device__ __forceinline__ float f_tf32(float x) {
    uint32_t r;
    asm("cvt.rna.tf32.f32 %0, %1;" : "=r"(r) : "f"(x));
    return __uint_as_float(r);
}
__device__ __forceinline__ void mma_tf32(float* c, const uint32_t* a, const uint32_t* b) {
    asm volatile(
        "mma.sync.aligned.m16n8k8.row.col.f32.tf32.tf32.f32 "
        "{%0,%1,%2,%3},{%4,%5,%6,%7},{%8,%9},{%0,%1,%2,%3};"
        : "+f"(c[0]), "+f"(c[1]), "+f"(c[2]), "+f"(c[3])
        : "r"(a[0]), "r"(a[1]), "r"(a[2]), "r"(a[3]), "r"(b[0]), "r"(b[1]));
}

// ---------------- 3xTF32 tensor-core GEMM (fp32-accurate) ----------------
// C = epi(A[M,K] @ op(B) + bias). EPI: 0=none, 1=gelu(tanh), 2=+residual add[m,n]
// TRANSB=false: B is [K,N] row-major. TRANSB=true: B is [N,K] row-major.
// Each input split hi/lo in tf32; per product: hi*hi + hi*lo + lo*hi.
// Block tile 128x128x16, 8 warps each 64x32 via m16n8k8.
template<int EPI, bool TRANSB>
__global__ __launch_bounds__(256) void mma_gemm(const float* __restrict__ A,
                                                const float* __restrict__ B,
                                                const float* __restrict__ bias,
                                                const float* __restrict__ add,
                                                float* __restrict__ C,
                                                int M, int N, int K) {
    constexpr int BM = 128, BN = 128, BK = 16;
    constexpr int AST = 20;                       // As row stride (floats)
    constexpr int BST = TRANSB ? 20 : 136;        // Bs row stride
    constexpr int BSZ = TRANSB ? (BN * 20) : (BK * 136);
    __shared__ float Ah[BM * AST], Al[BM * AST];
    __shared__ float Bh[BSZ], Bl[BSZ];

    int tid  = threadIdx.x;
    int wid  = tid >> 5, lane = tid & 31;
    int wr   = wid >> 2, wc = wid & 3;            // warp grid 2 x 4
    int g    = lane >> 2, tg = lane & 3;          // groupID, thread-in-group
    int row0 = blockIdx.y * BM, col0 = blockIdx.x * BN;

    float c[4][4][4];
    #pragma unroll
    for (int mi = 0; mi < 4; mi++)
        #pragma unroll
        for (int ni = 0; ni < 4; ni++)
            #pragma unroll
            for (int r = 0; r < 4; r++) c[mi][ni][r] = 0.f;

    for (int k0 = 0; k0 < K; k0 += BK) {
        // ---- stage A tile [128 x 16] hi/lo ----
        {
            int r = tid >> 2, cc = (tid & 3) * 4;
            #pragma unroll
            for (int i = 0; i < 2; i++) {
                float4 v = *(const float4*)(A + (size_t)(row0 + r + i * 64) * K + k0 + cc);
                int idx = (r + i * 64) * AST + cc;
                float h0 = f_tf32(v.x), h1 = f_tf32(v.y), h2 = f_tf32(v.z), h3 = f_tf32(v.w);
                Ah[idx+0] = h0; Ah[idx+1] = h1; Ah[idx+2] = h2; Ah[idx+3] = h3;
                Al[idx+0] = f_tf32(v.x - h0); Al[idx+1] = f_tf32(v.y - h1);
                Al[idx+2] = f_tf32(v.z - h2); Al[idx+3] = f_tf32(v.w - h3);
            }
        }
        // ---- stage B tile hi/lo ----
        if (!TRANSB) {  // B[K,N]: Bs[k][n], 16 x 128
            int r = tid >> 5, cc = (tid & 31) * 4;
            #pragma unroll
            for (int i = 0; i < 2; i++) {
                float4 v = *(const float4*)(B + (size_t)(k0 + r + i * 8) * N + col0 + cc);
                int idx = (r + i * 8) * BST + cc;
                float h0 = f_tf32(v.x), h1 = f_tf32(v.y), h2 = f_tf32(v.z), h3 = f_tf32(v.w);
                Bh[idx+0] = h0; Bh[idx+1] = h1; Bh[idx+2] = h2; Bh[idx+3] = h3;
                Bl[idx+0] = f_tf32(v.x - h0); Bl[idx+1] = f_tf32(v.y - h1);
                Bl[idx+2] = f_tf32(v.z - h2); Bl[idx+3] = f_tf32(v.w - h3);
            }
        } else {        // B[N,K]: Bs[n][k], 128 x 16
            int n = tid >> 2, cc = (tid & 3) * 4;
            #pragma unroll
            for (int i = 0; i < 2; i++) {
                float4 v = *(const float4*)(B + (size_t)(col0 + n + i * 64) * K + k0 + cc);
                int idx = (n + i * 64) * BST + cc;
                float h0 = f_tf32(v.x), h1 = f_tf32(v.y), h2 = f_tf32(v.z), h3 = f_tf32(v.w);
                Bh[idx+0] = h0; Bh[idx+1] = h1; Bh[idx+2] = h2; Bh[idx+3] = h3;
                Bl[idx+0] = f_tf32(v.x - h0); Bl[idx+1] = f_tf32(v.y - h1);
                Bl[idx+2] = f_tf32(v.z - h2); Bl[idx+3] = f_tf32(v.w - h3);
            }
        }
        __syncthreads();

        #pragma unroll
        for (int ks = 0; ks < 2; ks++) {
            int kk = ks * 8;
            uint32_t ah[4][4], al[4][4], bh[4][2], bl[4][2];
            #pragma unroll
            for (int mi = 0; mi < 4; mi++) {
                int rb = wr * 64 + mi * 16;
                int i0 = (rb + g)     * AST + kk + tg;
                int i1 = (rb + g + 8) * AST + kk + tg;
                ah[mi][0] = __float_as_uint(Ah[i0]);
                ah[mi][1] = __float_as_uint(Ah[i1]);
                ah[mi][2] = __float_as_uint(Ah[i0 + 4]);
                ah[mi][3] = __float_as_uint(Ah[i1 + 4]);
                al[mi][0] = __float_as_uint(Al[i0]);
                al[mi][1] = __float_as_uint(Al[i1]);
                al[mi][2] = __float_as_uint(Al[i0 + 4]);
                al[mi][3] = __float_as_uint(Al[i1 + 4]);
            }
            #pragma unroll
            for (int ni = 0; ni < 4; ni++) {
                int cb = wc * 32 + ni * 8;
                if (!TRANSB) {
                    int i0 = (kk + tg)     * BST + cb + g;
                    int i1 = (kk + tg + 4) * BST + cb + g;
                    bh[ni][0] = __float_as_uint(Bh[i0]);
                    bh[ni][1] = __float_as_uint(Bh[i1]);
                    bl[ni][0] = __float_as_uint(Bl[i0]);
                    bl[ni][1] = __float_as_uint(Bl[i1]);
                } else {
                    int i0 = (cb + g) * BST + kk + tg;
                    bh[ni][0] = __float_as_uint(Bh[i0]);
                    bh[ni][1] = __float_as_uint(Bh[i0 + 4]);
                    bl[ni][0] = __float_as_uint(Bl[i0]);
                    bl[ni][1] = __float_as_uint(Bl[i0 + 4]);
                }
            }
            #pragma unroll
            for (int mi = 0; mi < 4; mi++)
                #pragma unroll
                for (int ni = 0; ni < 4; ni++) {
                    mma_tf32(c[mi][ni], ah[mi], bh[ni]);
                    mma_tf32(c[mi][ni], ah[mi], bl[ni]);
                    mma_tf32(c[mi][ni], al[mi], bh[ni]);
                }
        }
        __syncthreads();
    }

    // ---- epilogue ----
    #pragma unroll
    for (int mi = 0; mi < 4; mi++) {
        #pragma unroll
        for (int ni = 0; ni < 4; ni++) {
            int r0 = row0 + wr * 64 + mi * 16 + g;
            int cc = col0 + wc * 32 + ni * 8 + tg * 2;
            #pragma unroll
            for (int h = 0; h < 2; h++) {
                int r = r0 + h * 8;
                float v0 = c[mi][ni][h * 2 + 0];
                float v1 = c[mi][ni][h * 2 + 1];
                if (bias) { v0 += bias[cc]; v1 += bias[cc + 1]; }
                if (EPI == 1) {
                    float t0 = 0.7978845608028654f * (v0 + 0.044715f * v0 * v0 * v0);
                    v0 = 0.5f * v0 * (1.0f + tanhf(t0));
                    float t1 = 0.7978845608028654f * (v1 + 0.044715f * v1 * v1 * v1);
                    v1 = 0.5f * v1 * (1.0f + tanhf(t1));
                } else if (EPI == 2) {
                    const float2 a2 = *(const float2*)(add + (size_t)r * N + cc);
                    v0 += a2.x; v1 += a2.y;
                }
                float2 o2; o2.x = v0; o2.y = v1;
                *(float2*)(C + (size_t)r * N + cc) = o2;
            }
        }
    }
}

// ---------------- causal attention (flash-style, tile softmax, NO scaling) --
// grid: (T/128, H, B); block: 128 threads; thread = one query row.
__global__ __launch_bounds__(128) void attn_kernel(const float* __restrict__ qkv,
                                                   float* __restrict__ att) {
    int b = blockIdx.z, h = blockIdx.y;
    int q0 = blockIdx.x * 128;
    int tid = threadIdx.x;
    int qi = q0 + tid;

    __shared__ float Ks[32][HD];
    __shared__ float Vs[32][HD];

    const size_t base = (size_t)b * TSEQ * C3;
    const float* qp = qkv + base + (size_t)qi * C3 + h * HD;
    float q[HD];
    #pragma unroll
    for (int d = 0; d < HD; d++) q[d] = qp[d];

    float m = -1e30f, l = 0.f;
    float acc[HD];
    #pragma unroll
    for (int d = 0; d < HD; d++) acc[d] = 0.f;

    int kend = q0 + 128;
    for (int kj0 = 0; kj0 < kend; kj0 += 32) {
        __syncthreads();
        {   // cooperative load of 32 K rows and 32 V rows
            int jj = tid >> 2;
            int f0 = (tid & 3) * 4;
            const float* kp = qkv + base + (size_t)(kj0 + jj) * C3 + CDIM + h * HD;
            const float* vp = kp + CDIM;
            #pragma unroll
            for (int i = 0; i < 4; i++) {
                ((float4*)Ks[jj])[f0 + i] = ((const float4*)kp)[f0 + i];
                ((float4*)Vs[jj])[f0 + i] = ((const float4*)vp)[f0 + i];
            }
        }
        __syncthreads();

        int jlim = qi - kj0;
        float s[32];
        #pragma unroll
        for (int jj = 0; jj < 32; jj++) {
            float s0 = 0.f, s1 = 0.f, s2 = 0.f, s3 = 0.f;
            #pragma unroll
            for (int d = 0; d < HD; d += 4) {
                s0 += q[d]     * Ks[jj][d];
                s1 += q[d + 1] * Ks[jj][d + 1];
                s2 += q[d + 2] * Ks[jj][d + 2];
                s3 += q[d + 3] * Ks[jj][d + 3];
            }
            float sv = (s0 + s1) + (s2 + s3);
            s[jj] = (jj <= jlim) ? sv : -1e30f;
        }
        float tm = -1e30f;
        #pragma unroll
        for (int jj = 0; jj < 32; jj++) tm = fmaxf(tm, s[jj]);
        float nm = fmaxf(m, tm);
        float corr = __expf(m - nm);
        m = nm;
        float lsum = 0.f;
        #pragma unroll
        for (int jj = 0; jj < 32; jj++) {
            s[jj] = __expf(s[jj] - nm);
            lsum += s[jj];
        }
        l = l * corr + lsum;
        #pragma unroll
        for (int d = 0; d < HD; d++) acc[d] *= corr;
        #pragma unroll
        for (int jj = 0; jj < 32; jj++) {
            float p = s[jj];
            #pragma unroll
            for (int d = 0; d < HD; d++) acc[d] += p * Vs[jj][d];
        }
    }
    float inv = 1.f / l;
    float* o = att + (size_t)(b * TSEQ + qi) * CDIM + h * HD;
    #pragma unroll
    for (int d = 0; d < HD; d++) o[d] = acc[d] * inv;
}

// ---------------- per-row cross-entropy ----------------
__global__ __launch_bounds__(256) void loss_row_kernel(const float* __restrict__ logits,
                                                       const int* __restrict__ targets) {
    int row = blockIdx.x;
    const float* x = logits + (size_t)row * VOCAB;
    __shared__ float sh[8];
    float mx = -1e30f;
    for (int c = threadIdx.x; c < VOCAB; c += 256) mx = fmaxf(mx, x[c]);
    #pragma unroll
    for (int o = 16; o; o >>= 1) mx = fmaxf(mx, __shfl_down_sync(0xffffffffu, mx, o));
    if ((threadIdx.x & 31) == 0) sh[threadIdx.x >> 5] = mx;
    __syncthreads();
    if (threadIdx.x == 0) {
        float a = sh[0];
        #pragma unroll
        for (int i = 1; i < 8; i++) a = fmaxf(a, sh[i]);
        sh[0] = a;
    }
    __syncthreads();
    mx = sh[0];
    __syncthreads();
    float s = 0.f;
    for (int c = threadIdx.x; c < VOCAB; c += 256) s += expf(x[c] - mx);
    #pragma unroll
    for (int o = 16; o; o >>= 1) s += __shfl_down_sync(0xffffffffu, s, o);
    if ((threadIdx.x & 31) == 0) sh[threadIdx.x >> 5] = s;
    __syncthreads();
    if (threadIdx.x == 0) {
        float a = 0.f;
        #pragma unroll
        for (int i = 0; i < 8; i++) a += sh[i];
        g_rowloss[row] = (mx + logf(a)) - x[targets[row]];
    }
}

__global__ __launch_bounds__(1024) void loss_reduce_kernel(float* __restrict__ out) {
    __shared__ float sh[1024];
    int t = threadIdx.x;
    float s = 0.f;
    for (int i = t; i < NTOK; i += 1024) s += g_rowloss[i];
    sh[t] = s;
    __syncthreads();
    for (int o = 512; o; o >>= 1) {
        if (t < o) sh[t] += sh[t + o];
        __syncthreads();
    }
    if (t == 0) out[0] = sh[0] * (1.f / NTOK);
}

// ---------------- launch ----------------
extern "C" void kernel_launch(void* const* d_in, const int* in_sizes, int n_in,
                              void* d_out, int out_size) {
    const int*   x       = (const int*)  d_in[0];
    const int*   targets = (const int*)  d_in[1];
    const float* wte     = (const float*)d_in[2];
    const float* wpe     = (const float*)d_in[3];
    const float* ln1_w   = (const float*)d_in[4];
    const float* ln1_b   = (const float*)d_in[5];
    const float* attn_w  = (const float*)d_in[6];
    const float* attn_b  = (const float*)d_in[7];
    const float* proj_w  = (const float*)d_in[8];
    const float* proj_b  = (const float*)d_in[9];
    const float* ln2_w   = (const float*)d_in[10];
    const float* ln2_b   = (const float*)d_in[11];
    const float* fc_w    = (const float*)d_in[12];
    const float* fc_b    = (const float*)d_in[13];
    const float* fc2_w   = (const float*)d_in[14];
    const float* fc2_b   = (const float*)d_in[15];
    const float* lnf_w   = (const float*)d_in[16];
    const float* lnf_b   = (const float*)d_in[17];

    float* logits = (float*)d_out;
    float* lossp  = (float*)d_out + (out_size - 1);

    float *p_h, *p_hn, *p_qkv, *p_att, *p_fc;
    cudaGetSymbolAddress((void**)&p_h,   g_h);
    cudaGetSymbolAddress((void**)&p_hn,  g_hn);
    cudaGetSymbolAddress((void**)&p_qkv, g_qkv);
    cudaGetSymbolAddress((void**)&p_att, g_att);
    cudaGetSymbolAddress((void**)&p_fc,  g_fc);

    embed_kernel<<<NTOK, 256>>>(x, wte, wpe);

    for (int l = 0; l < NLAYER; l++) {
        ln_kernel<<<NTOK, 256>>>(p_h, ln1_w + (size_t)l * CDIM, ln1_b + (size_t)l * CDIM, p_hn);
        mma_gemm<0, false><<<dim3(C3 / 128, NTOK / 128), 256>>>(
            p_hn, attn_w + (size_t)l * CDIM * C3, attn_b + (size_t)l * C3,
            nullptr, p_qkv, NTOK, C3, CDIM);
        attn_kernel<<<dim3(TSEQ / 128, NHEAD, BATCH), 128>>>(p_qkv, p_att);
        mma_gemm<2, false><<<dim3(CDIM / 128, NTOK / 128), 256>>>(
            p_att, proj_w + (size_t)l * CDIM * CDIM, proj_b + (size_t)l * CDIM,
            p_h, p_h, NTOK, CDIM, CDIM);
        ln_kernel<<<NTOK, 256>>>(p_h, ln2_w + (size_t)l * CDIM, ln2_b + (size_t)l * CDIM, p_hn);
        mma_gemm<1, false><<<dim3(C4 / 128, NTOK / 128), 256>>>(
            p_hn, fc_w + (size_t)l * CDIM * C4, fc_b + (size_t)l * C4,
            nullptr, p_fc, NTOK, C4, CDIM);
        mma_gemm<2, false><<<dim3(CDIM / 128, NTOK / 128), 256>>>(
            p_fc, fc2_w + (size_t)l * C4 * CDIM, fc2_b + (size_t)l * CDIM,
            p_h, p_h, NTOK, CDIM, C4);
    }

    ln_kernel<<<NTOK, 256>>>(p_h, lnf_w, lnf_b, p_hn);
    mma_gemm<0, true><<<dim3(VOCAB / 128, NTOK / 128), 256>>>(
        p_hn, wte, nullptr, nullptr, logits, NTOK, VOCAB, CDIM);

    loss_row_kernel<<<NTOK, 256>>>(logits, targets);
    loss_reduce_kernel<<<1, 1024>>>(lossp);
}

// round 6
// speedup vs baseline: 1.6637x; 1.2247x over previous
#include <cuda_runtime.h>
#include <cuda_bf16.h>
#include <math.h>
#include <stdint.h>

// ---------------- problem constants ----------------
#define BATCH 4
#define TSEQ  1024
#define CDIM  768
#define NHEAD 12
#define HD    64
#define VOCAB 50304
#define NLAYER 12
#define NTOK  (BATCH*TSEQ)     // 4096
#define C3    (3*CDIM)         // 2304
#define C4    (4*CDIM)         // 3072

// ---------------- scratch (static device globals; no allocation allowed) ----
__device__ float g_h   [NTOK * CDIM];
__device__ float g_hn  [NTOK * CDIM];
__device__ float g_qkv [NTOK * C3];
__device__ float g_att [NTOK * CDIM];
__device__ float g_fc  [NTOK * C4];
__device__ float g_rowloss[NTOK];

// ---------------- embedding: h = wte[x] + wpe[t] ----------------
__global__ __launch_bounds__(256) void embed_kernel(const int* __restrict__ x,
                                                    const float* __restrict__ wte,
                                                    const float* __restrict__ wpe) {
    int m = blockIdx.x;
    int t = m % TSEQ;
    int idx = x[m];
    const float* we = wte + (size_t)idx * CDIM;
    const float* wp = wpe + (size_t)t * CDIM;
    float* o = g_h + (size_t)m * CDIM;
    for (int c = threadIdx.x; c < CDIM; c += 256)
        o[c] = we[c] + wp[c];
}

// ---------------- layernorm (block per row) ----------------
__global__ __launch_bounds__(256) void ln_kernel(const float* __restrict__ in,
                                                 const float* __restrict__ w,
                                                 const float* __restrict__ bb,
                                                 float* __restrict__ out) {
    int row = blockIdx.x;
    const float* x = in + (size_t)row * CDIM;
    float s = 0.f, s2 = 0.f;
    for (int c = threadIdx.x; c < CDIM; c += 256) {
        float v = x[c]; s += v; s2 += v * v;
    }
    __shared__ float ss[8], ss2[8];
    #pragma unroll
    for (int o = 16; o; o >>= 1) {
        s  += __shfl_down_sync(0xffffffffu, s,  o);
        s2 += __shfl_down_sync(0xffffffffu, s2, o);
    }
    if ((threadIdx.x & 31) == 0) { ss[threadIdx.x >> 5] = s; ss2[threadIdx.x >> 5] = s2; }
    __syncthreads();
    if (threadIdx.x == 0) {
        float a = 0.f, a2 = 0.f;
        #pragma unroll
        for (int i = 0; i < 8; i++) { a += ss[i]; a2 += ss2[i]; }
        ss[0] = a; ss2[0] = a2;
    }
    __syncthreads();
    float mean = ss[0] * (1.f / CDIM);
    float var  = ss2[0] * (1.f / CDIM) - mean * mean;
    float rstd = rsqrtf(var + 1e-5f);
    float* o = out + (size_t)row * CDIM;
    for (int c = threadIdx.x; c < CDIM; c += 256)
        o[c] = (x[c] - mean) * rstd * w[c] + bb[c];
}

// ---------------- epilogue helper ----------------
template<int EPI>
__device__ __forceinline__ void epi_store(float* __restrict__ C,
                                          const float* __restrict__ bias,
                                          const float* __restrict__ add,
                                          int r, int cc, int N, float v0, float v1) {
    if (bias) { v0 += bias[cc]; v1 += bias[cc + 1]; }
    if (EPI == 1) {
        float t0 = 0.7978845608028654f * (v0 + 0.044715f * v0 * v0 * v0);
        v0 = 0.5f * v0 * (1.0f + tanhf(t0));
        float t1 = 0.7978845608028654f * (v1 + 0.044715f * v1 * v1 * v1);
        v1 = 0.5f * v1 * (1.0f + tanhf(t1));
    } else if (EPI == 2) {
        const float2 a2 = *(const float2*)(add + (size_t)r * N + cc);
        v0 += a2.x; v1 += a2.y;
    }
    float2 o2; o2.x = v0; o2.y = v1;
    *(float2*)(C + (size_t)r * N + cc) = o2;
}

// ---------------- bf16 split helpers ----------------
__device__ __forceinline__ void bsplit(float x, uint16_t& h, uint16_t& l) {
    __nv_bfloat16 bh = __float2bfloat16_rn(x);
    h = __bfloat16_as_ushort(bh);
    float r = x - __bfloat162float(bh);
    l = __bfloat16_as_ushort(__float2bfloat16_rn(r));
}
__device__ __forceinline__ void mma_bf16(float* c, const uint32_t* a, const uint32_t* b) {
    asm volatile(
        "mma.sync.aligned.m16n8k16.row.col.f32.bf16.bf16.f32 "
        "{%0,%1,%2,%3},{%4,%5,%6,%7},{%8,%9},{%0,%1,%2,%3};"
        : "+f"(c[0]), "+f"(c[1]), "+f"(c[2]), "+f"(c[3])
        : "r"(a[0]), "r"(a[1]), "r"(a[2]), "r"(a[3]), "r"(b[0]), "r"(b[1]));
}

// ---------------- 3xBF16 trunk GEMM (fp32-class accuracy) ----------------
// C = epi(A[M,K] @ B[K,N] + bias). Per product: hi*hi + hi*lo + lo*hi.
// Block tile 128x128x32, 8 warps each 64x32 via m16n8k16.
template<int EPI>
__global__ __launch_bounds__(256) void bf16_gemm(const float* __restrict__ A,
                                                 const float* __restrict__ B,
                                                 const float* __restrict__ bias,
                                                 const float* __restrict__ add,
                                                 float* __restrict__ C,
                                                 int M, int N, int K) {
    constexpr int BM = 128, BN = 128, BK = 32;
    constexpr int ST = 40;   // padded row stride (bf16 elems) -> conflict-free frags
    __shared__ __nv_bfloat16 Ah[BM * ST], Al[BM * ST];
    __shared__ __nv_bfloat16 Bh[BN * ST], Bl[BN * ST];   // stored [n][k]

    int tid  = threadIdx.x;
    int wid  = tid >> 5, lane = tid & 31;
    int wr   = wid >> 2, wc = wid & 3;            // warp grid 2 x 4
    int g    = lane >> 2, tg = lane & 3;          // groupID, thread-in-group
    int row0 = blockIdx.y * BM, col0 = blockIdx.x * BN;

    float c[4][4][4];
    #pragma unroll
    for (int mi = 0; mi < 4; mi++)
        #pragma unroll
        for (int ni = 0; ni < 4; ni++)
            #pragma unroll
            for (int r = 0; r < 4; r++) c[mi][ni][r] = 0.f;

    for (int k0 = 0; k0 < K; k0 += BK) {
        // ---- stage A [128 x 32] ----
        {
            int am = tid >> 3, ak = (tid & 7) * 4;
            #pragma unroll
            for (int i = 0; i < 4; i++) {
                float4 v = *(const float4*)(A + (size_t)(row0 + am + i * 32) * K + k0 + ak);
                uint16_t h0,l0,h1,l1,h2,l2,h3,l3;
                bsplit(v.x,h0,l0); bsplit(v.y,h1,l1); bsplit(v.z,h2,l2); bsplit(v.w,h3,l3);
                int idx = (am + i * 32) * ST + ak;
                *(uint32_t*)&Ah[idx]     = (uint32_t)h0 | ((uint32_t)h1 << 16);
                *(uint32_t*)&Ah[idx + 2] = (uint32_t)h2 | ((uint32_t)h3 << 16);
                *(uint32_t*)&Al[idx]     = (uint32_t)l0 | ((uint32_t)l1 << 16);
                *(uint32_t*)&Al[idx + 2] = (uint32_t)l2 | ((uint32_t)l3 << 16);
            }
        }
        // ---- stage B [K,N] global -> Bs[n][k] ----
        {
            int n  = tid & 127;
            int kb = (tid >> 7) * 16;
            float bv[16];
            #pragma unroll
            for (int j = 0; j < 16; j++)
                bv[j] = B[(size_t)(k0 + kb + j) * N + col0 + n];
            #pragma unroll
            for (int j = 0; j < 8; j++) {
                uint16_t h0,l0,h1,l1;
                bsplit(bv[2*j],h0,l0); bsplit(bv[2*j+1],h1,l1);
                int idx = n * ST + kb + 2 * j;
                *(uint32_t*)&Bh[idx] = (uint32_t)h0 | ((uint32_t)h1 << 16);
                *(uint32_t*)&Bl[idx] = (uint32_t)l0 | ((uint32_t)l1 << 16);
            }
        }
        __syncthreads();

        #pragma unroll
        for (int ks = 0; ks < 2; ks++) {
            int kk = ks * 16;
            uint32_t ah[4][4], al[4][4], bh[4][2], bl[4][2];
            #pragma unroll
            for (int mi = 0; mi < 4; mi++) {
                int r1 = (wr * 64 + mi * 16 + g) * ST + kk + 2 * tg;
                int r2 = r1 + 8 * ST;
                ah[mi][0] = *(const uint32_t*)&Ah[r1];
                ah[mi][1] = *(const uint32_t*)&Ah[r2];
                ah[mi][2] = *(const uint32_t*)&Ah[r1 + 8];
                ah[mi][3] = *(const uint32_t*)&Ah[r2 + 8];
                al[mi][0] = *(const uint32_t*)&Al[r1];
                al[mi][1] = *(const uint32_t*)&Al[r2];
                al[mi][2] = *(const uint32_t*)&Al[r1 + 8];
                al[mi][3] = *(const uint32_t*)&Al[r2 + 8];
            }
            #pragma unroll
            for (int ni = 0; ni < 4; ni++) {
                int n1 = (wc * 32 + ni * 8 + g) * ST + kk + 2 * tg;
                bh[ni][0] = *(const uint32_t*)&Bh[n1];
                bh[ni][1] = *(const uint32_t*)&Bh[n1 + 8];
                bl[ni][0] = *(const uint32_t*)&Bl[n1];
                bl[ni][1] = *(const uint32_t*)&Bl[n1 + 8];
            }
            #pragma unroll
            for (int mi = 0; mi < 4; mi++)
                #pragma unroll
                for (int ni = 0; ni < 4; ni++) {
                    mma_bf16(c[mi][ni], ah[mi], bh[ni]);
                    mma_bf16(c[mi][ni], ah[mi], bl[ni]);
                    mma_bf16(c[mi][ni], al[mi], bh[ni]);
                }
        }
        __syncthreads();
    }

    #pragma unroll
    for (int mi = 0; mi < 4; mi++)
        #pragma unroll
        for (int ni = 0; ni < 4; ni++) {
            int r0 = row0 + wr * 64 + mi * 16 + g;
            int cc = col0 + wc * 32 + ni * 8 + tg * 2;
            epi_store<EPI>(C, bias, add, r0,     cc, N, c[mi][ni][0], c[mi][ni][1]);
            epi_store<EPI>(C, bias, add, r0 + 8, cc, N, c[mi][ni][2], c[mi][ni][3]);
        }
}

// ---------------- tf32 helpers (LM head keeps 3xTF32 precision) ------------
__device__ __forceinline__ float f_tf32(float x) {
    uint32_t r;
    asm("cvt.rna.tf32.f32 %0, %1;" : "=r"(r) : "f"(x));
    return __uint_as_float(r);
}
__device__ __forceinline__ void mma_tf32(float* c, const uint32_t* a, const uint32_t* b) {
    asm volatile(
        "mma.sync.aligned.m16n8k8.row.col.f32.tf32.tf32.f32 "
        "{%0,%1,%2,%3},{%4,%5,%6,%7},{%8,%9},{%0,%1,%2,%3};"
        : "+f"(c[0]), "+f"(c[1]), "+f"(c[2]), "+f"(c[3])
        : "r"(a[0]), "r"(a[1]), "r"(a[2]), "r"(a[3]), "r"(b[0]), "r"(b[1]));
}

// ---------------- 3xTF32 GEMM for tied LM head (B is [N,K] row-major) ------
__global__ __launch_bounds__(256) void head_gemm(const float* __restrict__ A,
                                                 const float* __restrict__ B,
                                                 float* __restrict__ C,
                                                 int M, int N, int K) {
    constexpr int BM = 128, BN = 128, BK = 16;
    constexpr int AST = 20, BST = 20;
    __shared__ float Ah[BM * AST], Al[BM * AST];
    __shared__ float Bh[BN * BST], Bl[BN * BST];

    int tid  = threadIdx.x;
    int wid  = tid >> 5, lane = tid & 31;
    int wr   = wid >> 2, wc = wid & 3;
    int g    = lane >> 2, tg = lane & 3;
    int row0 = blockIdx.y * BM, col0 = blockIdx.x * BN;

    float c[4][4][4];
    #pragma unroll
    for (int mi = 0; mi < 4; mi++)
        #pragma unroll
        for (int ni = 0; ni < 4; ni++)
            #pragma unroll
            for (int r = 0; r < 4; r++) c[mi][ni][r] = 0.f;

    for (int k0 = 0; k0 < K; k0 += BK) {
        {
            int r = tid >> 2, cc = (tid & 3) * 4;
            #pragma unroll
            for (int i = 0; i < 2; i++) {
                float4 v = *(const float4*)(A + (size_t)(row0 + r + i * 64) * K + k0 + cc);
                int idx = (r + i * 64) * AST + cc;
                float h0 = f_tf32(v.x), h1 = f_tf32(v.y), h2 = f_tf32(v.z), h3 = f_tf32(v.w);
                Ah[idx+0] = h0; Ah[idx+1] = h1; Ah[idx+2] = h2; Ah[idx+3] = h3;
                Al[idx+0] = f_tf32(v.x - h0); Al[idx+1] = f_tf32(v.y - h1);
                Al[idx+2] = f_tf32(v.z - h2); Al[idx+3] = f_tf32(v.w - h3);
            }
        }
        {
            int n = tid >> 2, cc = (tid & 3) * 4;
            #pragma unroll
            for (int i = 0; i < 2; i++) {
                float4 v = *(const float4*)(B + (size_t)(col0 + n + i * 64) * K + k0 + cc);
                int idx = (n + i * 64) * BST + cc;
                float h0 = f_tf32(v.x), h1 = f_tf32(v.y), h2 = f_tf32(v.z), h3 = f_tf32(v.w);
                Bh[idx+0] = h0; Bh[idx+1] = h1; Bh[idx+2] = h2; Bh[idx+3] = h3;
                Bl[idx+0] = f_tf32(v.x - h0); Bl[idx+1] = f_tf32(v.y - h1);
                Bl[idx+2] = f_tf32(v.z - h2); Bl[idx+3] = f_tf32(v.w - h3);
            }
        }
        __syncthreads();

        #pragma unroll
        for (int ks = 0; ks < 2; ks++) {
            int kk = ks * 8;
            uint32_t ah[4][4], al[4][4], bh[4][2], bl[4][2];
            #pragma unroll
            for (int mi = 0; mi < 4; mi++) {
                int i0 = (wr * 64 + mi * 16 + g) * AST + kk + tg;
                int i1 = i0 + 8 * AST;
                ah[mi][0] = __float_as_uint(Ah[i0]);
                ah[mi][1] = __float_as_uint(Ah[i1]);
                ah[mi][2] = __float_as_uint(Ah[i0 + 4]);
                ah[mi][3] = __float_as_uint(Ah[i1 + 4]);
                al[mi][0] = __float_as_uint(Al[i0]);
                al[mi][1] = __float_as_uint(Al[i1]);
                al[mi][2] = __float_as_uint(Al[i0 + 4]);
                al[mi][3] = __float_as_uint(Al[i1 + 4]);
            }
            #pragma unroll
            for (int ni = 0; ni < 4; ni++) {
                int i0 = (wc * 32 + ni * 8 + g) * BST + kk + tg;
                bh[ni][0] = __float_as_uint(Bh[i0]);
                bh[ni][1] = __float_as_uint(Bh[i0 + 4]);
                bl[ni][0] = __float_as_uint(Bl[i0]);
                bl[ni][1] = __float_as_uint(Bl[i0 + 4]);
            }
            #pragma unroll
            for (int mi = 0; mi < 4; mi++)
                #pragma unroll
                for (int ni = 0; ni < 4; ni++) {
                    mma_tf32(c[mi][ni], ah[mi], bh[ni]);
                    mma_tf32(c[mi][ni], ah[mi], bl[ni]);
                    mma_tf32(c[mi][ni], al[mi], bh[ni]);
                }
        }
        __syncthreads();
    }

    #pragma unroll
    for (int mi = 0; mi < 4; mi++)
        #pragma unroll
        for (int ni = 0; ni < 4; ni++) {
            int r0 = row0 + wr * 64 + mi * 16 + g;
            int cc = col0 + wc * 32 + ni * 8 + tg * 2;
            epi_store<0>(C, nullptr, nullptr, r0,     cc, N, c[mi][ni][0], c[mi][ni][1]);
            epi_store<0>(C, nullptr, nullptr, r0 + 8, cc, N, c[mi][ni][2], c[mi][ni][3]);
        }
}

// ---------------- causal attention (flash-style, tile softmax, NO scaling) --
// grid: (T/128, H, B); block: 128 threads; thread = one query row.
__global__ __launch_bounds__(128) void attn_kernel(const float* __restrict__ qkv,
                                                   float* __restrict__ att) {
    int b = blockIdx.z, h = blockIdx.y;
    int q0 = blockIdx.x * 128;
    int tid = threadIdx.x;
    int qi = q0 + tid;

    __shared__ float Ks[32][HD];
    __shared__ float Vs[32][HD];

    const size_t base = (size_t)b * TSEQ * C3;
    const float* qp = qkv + base + (size_t)qi * C3 + h * HD;
    float q[HD];
    #pragma unroll
    for (int d = 0; d < HD; d++) q[d] = qp[d];

    float m = -1e30f, l = 0.f;
    float acc[HD];
    #pragma unroll
    for (int d = 0; d < HD; d++) acc[d] = 0.f;

    int kend = q0 + 128;
    for (int kj0 = 0; kj0 < kend; kj0 += 32) {
        __syncthreads();
        {   // cooperative load of 32 K rows and 32 V rows
            int jj = tid >> 2;
            int f0 = (tid & 3) * 4;
            const float* kp = qkv + base + (size_t)(kj0 + jj) * C3 + CDIM + h * HD;
            const float* vp = kp + CDIM;
            #pragma unroll
            for (int i = 0; i < 4; i++) {
                ((float4*)Ks[jj])[f0 + i] = ((const float4*)kp)[f0 + i];
                ((float4*)Vs[jj])[f0 + i] = ((const float4*)vp)[f0 + i];
            }
        }
        __syncthreads();

        int jlim = qi - kj0;
        float s[32];
        #pragma unroll
        for (int jj = 0; jj < 32; jj++) {
            const float4* k4 = (const float4*)Ks[jj];
            float s0 = 0.f, s1 = 0.f, s2 = 0.f, s3 = 0.f;
            #pragma unroll
            for (int dd = 0; dd < HD / 4; dd++) {
                float4 kv = k4[dd];
                s0 += q[dd * 4 + 0] * kv.x;
                s1 += q[dd * 4 + 1] * kv.y;
                s2 += q[dd * 4 + 2] * kv.z;
                s3 += q[dd * 4 + 3] * kv.w;
            }
            float sv = (s0 + s1) + (s2 + s3);
            s[jj] = (jj <= jlim) ? sv : -1e30f;
        }
        float tm = -1e30f;
        #pragma unroll
        for (int jj = 0; jj < 32; jj++) tm = fmaxf(tm, s[jj]);
        float nm = fmaxf(m, tm);
        float corr = __expf(m - nm);
        m = nm;
        float lsum = 0.f;
        #pragma unroll
        for (int jj = 0; jj < 32; jj++) {
            s[jj] = __expf(s[jj] - nm);
            lsum += s[jj];
        }
        l = l * corr + lsum;
        #pragma unroll
        for (int d = 0; d < HD; d++) acc[d] *= corr;
        #pragma unroll
        for (int jj = 0; jj < 32; jj++) {
            float p = s[jj];
            const float4* v4 = (const float4*)Vs[jj];
            #pragma unroll
            for (int dd = 0; dd < HD / 4; dd++) {
                float4 vv = v4[dd];
                acc[dd * 4 + 0] += p * vv.x;
                acc[dd * 4 + 1] += p * vv.y;
                acc[dd * 4 + 2] += p * vv.z;
                acc[dd * 4 + 3] += p * vv.w;
            }
        }
    }
    float inv = 1.f / l;
    float* o = att + (size_t)(b * TSEQ + qi) * CDIM + h * HD;
    #pragma unroll
    for (int d = 0; d < HD; d++) o[d] = acc[d] * inv;
}

// ---------------- per-row cross-entropy ----------------
__global__ __launch_bounds__(256) void loss_row_kernel(const float* __restrict__ logits,
                                                       const int* __restrict__ targets) {
    int row = blockIdx.x;
    const float* x = logits + (size_t)row * VOCAB;
    __shared__ float sh[8];
    float mx = -1e30f;
    for (int c = threadIdx.x; c < VOCAB; c += 256) mx = fmaxf(mx, x[c]);
    #pragma unroll
    for (int o = 16; o; o >>= 1) mx = fmaxf(mx, __shfl_down_sync(0xffffffffu, mx, o));
    if ((threadIdx.x & 31) == 0) sh[threadIdx.x >> 5] = mx;
    __syncthreads();
    if (threadIdx.x == 0) {
        float a = sh[0];
        #pragma unroll
        for (int i = 1; i < 8; i++) a = fmaxf(a, sh[i]);
        sh[0] = a;
    }
    __syncthreads();
    mx = sh[0];
    __syncthreads();
    float s = 0.f;
    for (int c = threadIdx.x; c < VOCAB; c += 256) s += expf(x[c] - mx);
    #pragma unroll
    for (int o = 16; o; o >>= 1) s += __shfl_down_sync(0xffffffffu, s, o);
    if ((threadIdx.x & 31) == 0) sh[threadIdx.x >> 5] = s;
    __syncthreads();
    if (threadIdx.x == 0) {
        float a = 0.f;
        #pragma unroll
        for (int i = 0; i < 8; i++) a += sh[i];
        g_rowloss[row] = (mx + logf(a)) - x[targets[row]];
    }
}

__global__ __launch_bounds__(1024) void loss_reduce_kernel(float* __restrict__ out) {
    __shared__ float sh[1024];
    int t = threadIdx.x;
    float s = 0.f;
    for (int i = t; i < NTOK; i += 1024) s += g_rowloss[i];
    sh[t] = s;
    __syncthreads();
    for (int o = 512; o; o >>= 1) {
        if (t < o) sh[t] += sh[t + o];
        __syncthreads();
    }
    if (t == 0) out[0] = sh[0] * (1.f / NTOK);
}

// ---------------- launch ----------------
extern "C" void kernel_launch(void* const* d_in, const int* in_sizes, int n_in,
                              void* d_out, int out_size) {
    const int*   x       = (const int*)  d_in[0];
    const int*   targets = (const int*)  d_in[1];
    const float* wte     = (const float*)d_in[2];
    const float* wpe     = (const float*)d_in[3];
    const float* ln1_w   = (const float*)d_in[4];
    const float* ln1_b   = (const float*)d_in[5];
    const float* attn_w  = (const float*)d_in[6];
    const float* attn_b  = (const float*)d_in[7];
    const float* proj_w  = (const float*)d_in[8];
    const float* proj_b  = (const float*)d_in[9];
    const float* ln2_w   = (const float*)d_in[10];
    const float* ln2_b   = (const float*)d_in[11];
    const float* fc_w    = (const float*)d_in[12];
    const float* fc_b    = (const float*)d_in[13];
    const float* fc2_w   = (const float*)d_in[14];
    const float* fc2_b   = (const float*)d_in[15];
    const float* lnf_w   = (const float*)d_in[16];
    const float* lnf_b   = (const float*)d_in[17];

    float* logits = (float*)d_out;
    float* lossp  = (float*)d_out + (out_size - 1);

    float *p_h, *p_hn, *p_qkv, *p_att, *p_fc;
    cudaGetSymbolAddress((void**)&p_h,   g_h);
    cudaGetSymbolAddress((void**)&p_hn,  g_hn);
    cudaGetSymbolAddress((void**)&p_qkv, g_qkv);
    cudaGetSymbolAddress((void**)&p_att, g_att);
    cudaGetSymbolAddress((void**)&p_fc,  g_fc);

    embed_kernel<<<NTOK, 256>>>(x, wte, wpe);

    for (int l = 0; l < NLAYER; l++) {
        ln_kernel<<<NTOK, 256>>>(p_h, ln1_w + (size_t)l * CDIM, ln1_b + (size_t)l * CDIM, p_hn);
        bf16_gemm<0><<<dim3(C3 / 128, NTOK / 128), 256>>>(
            p_hn, attn_w + (size_t)l * CDIM * C3, attn_b + (size_t)l * C3,
            nullptr, p_qkv, NTOK, C3, CDIM);
        attn_kernel<<<dim3(TSEQ / 128, NHEAD, BATCH), 128>>>(p_qkv, p_att);
        bf16_gemm<2><<<dim3(CDIM / 128, NTOK / 128), 256>>>(
            p_att, proj_w + (size_t)l * CDIM * CDIM, proj_b + (size_t)l * CDIM,
            p_h, p_h, NTOK, CDIM, CDIM);
        ln_kernel<<<NTOK, 256>>>(p_h, ln2_w + (size_t)l * CDIM, ln2_b + (size_t)l * CDIM, p_hn);
        bf16_gemm<1><<<dim3(C4 / 128, NTOK / 128), 256>>>(
            p_hn, fc_w + (size_t)l * CDIM * C4, fc_b + (size_t)l * C4,
            nullptr, p_fc, NTOK, C4, CDIM);
        bf16_gemm<2><<<dim3(CDIM / 128, NTOK / 128), 256>>>(
            p_fc, fc2_w + (size_t)l * C4 * CDIM, fc2_b + (size_t)l * CDIM,
            p_h, p_h, NTOK, CDIM, C4);
    }

    ln_kernel<<<NTOK, 256>>>(p_h, lnf_w, lnf_b, p_hn);
    head_gemm<<<dim3(VOCAB / 128, NTOK / 128), 256>>>(
        p_hn, wte, logits, NTOK, VOCAB, CDIM);

    loss_row_kernel<<<NTOK, 256>>>(logits, targets);
    loss_reduce_kernel<<<1, 1024>>>(lossp);
}

// round 7
// speedup vs baseline: 2.2209x; 1.3349x over previous
#include <cuda_runtime.h>
#include <cuda_bf16.h>
#include <math.h>
#include <stdint.h>

// ---------------- problem constants ----------------
#define BATCH 4
#define TSEQ  1024
#define CDIM  768
#define NHEAD 12
#define HD    64
#define VOCAB 50304
#define NLAYER 12
#define NTOK  (BATCH*TSEQ)     // 4096
#define C3    (3*CDIM)         // 2304
#define C4    (4*CDIM)         // 3072

// ---------------- scratch (static device globals; no allocation allowed) ----
__device__ float g_h   [NTOK * CDIM];
__device__ float g_hn  [NTOK * CDIM];
__device__ float g_qkv [NTOK * C3];
__device__ float g_att [NTOK * CDIM];
__device__ float g_fc  [NTOK * C4];
__device__ float g_rowloss[NTOK];

// ---------------- embedding: h = wte[x] + wpe[t] ----------------
__global__ __launch_bounds__(256) void embed_kernel(const int* __restrict__ x,
                                                    const float* __restrict__ wte,
                                                    const float* __restrict__ wpe) {
    int m = blockIdx.x;
    int t = m % TSEQ;
    int idx = x[m];
    const float* we = wte + (size_t)idx * CDIM;
    const float* wp = wpe + (size_t)t * CDIM;
    float* o = g_h + (size_t)m * CDIM;
    for (int c = threadIdx.x; c < CDIM; c += 256)
        o[c] = we[c] + wp[c];
}

// ---------------- layernorm (block per row) ----------------
__global__ __launch_bounds__(256) void ln_kernel(const float* __restrict__ in,
                                                 const float* __restrict__ w,
                                                 const float* __restrict__ bb,
                                                 float* __restrict__ out) {
    int row = blockIdx.x;
    const float* x = in + (size_t)row * CDIM;
    float s = 0.f, s2 = 0.f;
    for (int c = threadIdx.x; c < CDIM; c += 256) {
        float v = x[c]; s += v; s2 += v * v;
    }
    __shared__ float ss[8], ss2[8];
    #pragma unroll
    for (int o = 16; o; o >>= 1) {
        s  += __shfl_down_sync(0xffffffffu, s,  o);
        s2 += __shfl_down_sync(0xffffffffu, s2, o);
    }
    if ((threadIdx.x & 31) == 0) { ss[threadIdx.x >> 5] = s; ss2[threadIdx.x >> 5] = s2; }
    __syncthreads();
    if (threadIdx.x == 0) {
        float a = 0.f, a2 = 0.f;
        #pragma unroll
        for (int i = 0; i < 8; i++) { a += ss[i]; a2 += ss2[i]; }
        ss[0] = a; ss2[0] = a2;
    }
    __syncthreads();
    float mean = ss[0] * (1.f / CDIM);
    float var  = ss2[0] * (1.f / CDIM) - mean * mean;
    float rstd = rsqrtf(var + 1e-5f);
    float* o = out + (size_t)row * CDIM;
    for (int c = threadIdx.x; c < CDIM; c += 256)
        o[c] = (x[c] - mean) * rstd * w[c] + bb[c];
}

// ---------------- epilogue helper ----------------
template<int EPI>
__device__ __forceinline__ void epi_store(float* __restrict__ C,
                                          const float* __restrict__ bias,
                                          const float* __restrict__ add,
                                          int r, int cc, int N, float v0, float v1) {
    if (bias) { v0 += bias[cc]; v1 += bias[cc + 1]; }
    if (EPI == 1) {
        float t0 = 0.7978845608028654f * (v0 + 0.044715f * v0 * v0 * v0);
        v0 = 0.5f * v0 * (1.0f + tanhf(t0));
        float t1 = 0.7978845608028654f * (v1 + 0.044715f * v1 * v1 * v1);
        v1 = 0.5f * v1 * (1.0f + tanhf(t1));
    } else if (EPI == 2) {
        const float2 a2 = *(const float2*)(add + (size_t)r * N + cc);
        v0 += a2.x; v1 += a2.y;
    }
    float2 o2; o2.x = v0; o2.y = v1;
    *(float2*)(C + (size_t)r * N + cc) = o2;
}

// ---------------- bf16 split helpers ----------------
__device__ __forceinline__ void bsplit(float x, uint16_t& h, uint16_t& l) {
    __nv_bfloat16 bh = __float2bfloat16_rn(x);
    h = __bfloat16_as_ushort(bh);
    float r = x - __bfloat162float(bh);
    l = __bfloat16_as_ushort(__float2bfloat16_rn(r));
}
__device__ __forceinline__ void pack_hl(float vx, float vy, uint32_t& h, uint32_t& l) {
    uint16_t hx, lx, hy, ly;
    bsplit(vx, hx, lx); bsplit(vy, hy, ly);
    h = (uint32_t)hx | ((uint32_t)hy << 16);
    l = (uint32_t)lx | ((uint32_t)ly << 16);
}
__device__ __forceinline__ void mma_bf16(float* c, const uint32_t* a, const uint32_t* b) {
    asm volatile(
        "mma.sync.aligned.m16n8k16.row.col.f32.bf16.bf16.f32 "
        "{%0,%1,%2,%3},{%4,%5,%6,%7},{%8,%9},{%0,%1,%2,%3};"
        : "+f"(c[0]), "+f"(c[1]), "+f"(c[2]), "+f"(c[3])
        : "r"(a[0]), "r"(a[1]), "r"(a[2]), "r"(a[3]), "r"(b[0]), "r"(b[1]));
}

// ---------------- 3xBF16 GEMM (fp32-class accuracy) ----------------
// C = epi(A[M,K] @ op(B) + bias). Per product: hi*hi + hi*lo + lo*hi.
// TRANSB=false: B is [K,N]. TRANSB=true: B is [N,K] (tied LM head).
// Block tile 128x128x32, 8 warps each 64x32 via m16n8k16.
template<int EPI, bool TRANSB>
__global__ __launch_bounds__(256) void bf16_gemm(const float* __restrict__ A,
                                                 const float* __restrict__ B,
                                                 const float* __restrict__ bias,
                                                 const float* __restrict__ add,
                                                 float* __restrict__ C,
                                                 int M, int N, int K) {
    constexpr int BM = 128, BN = 128, BK = 32;
    constexpr int ST = 40;   // padded row stride (bf16 elems) -> conflict-free frags
    __shared__ __nv_bfloat16 Ah[BM * ST], Al[BM * ST];
    __shared__ __nv_bfloat16 Bh[BN * ST], Bl[BN * ST];   // stored [n][k]

    int tid  = threadIdx.x;
    int wid  = tid >> 5, lane = tid & 31;
    int wr   = wid >> 2, wc = wid & 3;            // warp grid 2 x 4
    int g    = lane >> 2, tg = lane & 3;          // groupID, thread-in-group
    int row0 = blockIdx.y * BM, col0 = blockIdx.x * BN;

    float c[4][4][4];
    #pragma unroll
    for (int mi = 0; mi < 4; mi++)
        #pragma unroll
        for (int ni = 0; ni < 4; ni++)
            #pragma unroll
            for (int r = 0; r < 4; r++) c[mi][ni][r] = 0.f;

    for (int k0 = 0; k0 < K; k0 += BK) {
        // ---- stage A [128 x 32] ----
        {
            int am = tid >> 3, ak = (tid & 7) * 4;
            #pragma unroll
            for (int i = 0; i < 4; i++) {
                float4 v = *(const float4*)(A + (size_t)(row0 + am + i * 32) * K + k0 + ak);
                int idx = (am + i * 32) * ST + ak;
                pack_hl(v.x, v.y, *(uint32_t*)&Ah[idx],     *(uint32_t*)&Al[idx]);
                pack_hl(v.z, v.w, *(uint32_t*)&Ah[idx + 2], *(uint32_t*)&Al[idx + 2]);
            }
        }
        // ---- stage B ----
        if (TRANSB) {   // B[N,K]: rows n, k-contiguous (same pattern as A)
            int bn = tid >> 3, bk = (tid & 7) * 4;
            #pragma unroll
            for (int i = 0; i < 4; i++) {
                float4 v = *(const float4*)(B + (size_t)(col0 + bn + i * 32) * K + k0 + bk);
                int idx = (bn + i * 32) * ST + bk;
                pack_hl(v.x, v.y, *(uint32_t*)&Bh[idx],     *(uint32_t*)&Bl[idx]);
                pack_hl(v.z, v.w, *(uint32_t*)&Bh[idx + 2], *(uint32_t*)&Bl[idx + 2]);
            }
        } else {        // B[K,N] -> Bs[n][k]
            int n  = tid & 127;
            int kb = (tid >> 7) * 16;
            float bv[16];
            #pragma unroll
            for (int j = 0; j < 16; j++)
                bv[j] = B[(size_t)(k0 + kb + j) * N + col0 + n];
            #pragma unroll
            for (int j = 0; j < 8; j++) {
                int idx = n * ST + kb + 2 * j;
                pack_hl(bv[2*j], bv[2*j+1], *(uint32_t*)&Bh[idx], *(uint32_t*)&Bl[idx]);
            }
        }
        __syncthreads();

        #pragma unroll
        for (int ks = 0; ks < 2; ks++) {
            int kk = ks * 16;
            uint32_t ah[4][4], al[4][4], bh[4][2], bl[4][2];
            #pragma unroll
            for (int mi = 0; mi < 4; mi++) {
                int r1 = (wr * 64 + mi * 16 + g) * ST + kk + 2 * tg;
                int r2 = r1 + 8 * ST;
                ah[mi][0] = *(const uint32_t*)&Ah[r1];
                ah[mi][1] = *(const uint32_t*)&Ah[r2];
                ah[mi][2] = *(const uint32_t*)&Ah[r1 + 8];
                ah[mi][3] = *(const uint32_t*)&Ah[r2 + 8];
                al[mi][0] = *(const uint32_t*)&Al[r1];
                al[mi][1] = *(const uint32_t*)&Al[r2];
                al[mi][2] = *(const uint32_t*)&Al[r1 + 8];
                al[mi][3] = *(const uint32_t*)&Al[r2 + 8];
            }
            #pragma unroll
            for (int ni = 0; ni < 4; ni++) {
                int n1 = (wc * 32 + ni * 8 + g) * ST + kk + 2 * tg;
                bh[ni][0] = *(const uint32_t*)&Bh[n1];
                bh[ni][1] = *(const uint32_t*)&Bh[n1 + 8];
                bl[ni][0] = *(const uint32_t*)&Bl[n1];
                bl[ni][1] = *(const uint32_t*)&Bl[n1 + 8];
            }
            #pragma unroll
            for (int mi = 0; mi < 4; mi++)
                #pragma unroll
                for (int ni = 0; ni < 4; ni++) {
                    mma_bf16(c[mi][ni], ah[mi], bh[ni]);
                    mma_bf16(c[mi][ni], ah[mi], bl[ni]);
                    mma_bf16(c[mi][ni], al[mi], bh[ni]);
                }
        }
        __syncthreads();
    }

    #pragma unroll
    for (int mi = 0; mi < 4; mi++)
        #pragma unroll
        for (int ni = 0; ni < 4; ni++) {
            int r0 = row0 + wr * 64 + mi * 16 + g;
            int cc = col0 + wc * 32 + ni * 8 + tg * 2;
            epi_store<EPI>(C, bias, add, r0,     cc, N, c[mi][ni][0], c[mi][ni][1]);
            epi_store<EPI>(C, bias, add, r0 + 8, cc, N, c[mi][ni][2], c[mi][ni][3]);
        }
}

// ---------------- MMA flash attention (3xBF16, causal, NO score scaling) ----
// grid: (T/128, H, B); block 256 = 8 warps; warp owns 16 q-rows.
// Subtile = 64 keys. K staged [key][d]; V staged transposed [d][key] in the
// SAME smem buffer (K phase then V phase). Softmax fp32 in registers.
__global__ __launch_bounds__(256) void attn_mma(const float* __restrict__ qkv,
                                                float* __restrict__ att) {
    constexpr int ST = 72;   // padded stride (bf16) -> conflict-free frag reads
    int b = blockIdx.z, h = blockIdx.y;
    int q0 = blockIdx.x * 128;
    int tid = threadIdx.x, wid = tid >> 5, lane = tid & 31;
    int g = lane >> 2, tg = lane & 3;
    int qw0 = q0 + wid * 16;
    const size_t base = (size_t)b * TSEQ * C3;

    __shared__ __nv_bfloat16 sH[64 * ST], sL[64 * ST];

    // ---- Q fragments (rows qw0+g, qw0+g+8), hi/lo ----
    uint32_t qh[4][4], ql[4][4];
    {
        const float* q_r0 = qkv + base + (size_t)(qw0 + g) * C3 + h * HD;
        const float* q_r1 = q_r0 + 8 * C3;
        #pragma unroll
        for (int s = 0; s < 4; s++) {
            float2 v0 = *(const float2*)(q_r0 + 16 * s + 2 * tg);
            float2 v1 = *(const float2*)(q_r1 + 16 * s + 2 * tg);
            float2 v2 = *(const float2*)(q_r0 + 16 * s + 2 * tg + 8);
            float2 v3 = *(const float2*)(q_r1 + 16 * s + 2 * tg + 8);
            pack_hl(v0.x, v0.y, qh[s][0], ql[s][0]);
            pack_hl(v1.x, v1.y, qh[s][1], ql[s][1]);
            pack_hl(v2.x, v2.y, qh[s][2], ql[s][2]);
            pack_hl(v3.x, v3.y, qh[s][3], ql[s][3]);
        }
    }

    float o[8][4];
    #pragma unroll
    for (int ni = 0; ni < 8; ni++)
        #pragma unroll
        for (int r = 0; r < 4; r++) o[ni][r] = 0.f;
    float m0 = -1e30f, m1 = -1e30f, l0 = 0.f, l1 = 0.f;

    int kend = q0 + 128;
    for (int j0 = 0; j0 < kend; j0 += 64) {
        bool act = (j0 <= qw0 + 15);
        __syncthreads();   // prior PV reads done before overwrite
        {   // ---- stage K [key][d] hi/lo ----
            int kk = tid >> 2, d0 = (tid & 3) * 16;
            const float* kp = qkv + base + (size_t)(j0 + kk) * C3 + CDIM + h * HD + d0;
            #pragma unroll
            for (int i = 0; i < 4; i++) {
                float4 v = ((const float4*)kp)[i];
                int idx = kk * ST + d0 + i * 4;
                pack_hl(v.x, v.y, *(uint32_t*)&sH[idx],     *(uint32_t*)&sL[idx]);
                pack_hl(v.z, v.w, *(uint32_t*)&sH[idx + 2], *(uint32_t*)&sL[idx + 2]);
            }
        }
        __syncthreads();

        uint32_t ph[4][4], pl[4][4];
        if (act) {
            // ---- S = Q @ K^T over 8 n-tiles x 4 k-steps ----
            float s[8][4];
            #pragma unroll
            for (int ni = 0; ni < 8; ni++) {
                s[ni][0] = s[ni][1] = s[ni][2] = s[ni][3] = 0.f;
                #pragma unroll
                for (int ss = 0; ss < 4; ss++) {
                    int ib = (8 * ni + g) * ST + 16 * ss + 2 * tg;
                    uint32_t bh[2] = { *(const uint32_t*)&sH[ib], *(const uint32_t*)&sH[ib + 8] };
                    uint32_t bl[2] = { *(const uint32_t*)&sL[ib], *(const uint32_t*)&sL[ib + 8] };
                    mma_bf16(s[ni], qh[ss], bh);
                    mma_bf16(s[ni], qh[ss], bl);
                    mma_bf16(s[ni], ql[ss], bh);
                }
            }
            // ---- causal mask + online softmax ----
            int r0 = qw0 + g, r1 = r0 + 8;
            float mx0 = -1e30f, mx1 = -1e30f;
            #pragma unroll
            for (int ni = 0; ni < 8; ni++) {
                int kc = j0 + 8 * ni + 2 * tg;
                if (kc     > r0) s[ni][0] = -1e30f;
                if (kc + 1 > r0) s[ni][1] = -1e30f;
                if (kc     > r1) s[ni][2] = -1e30f;
                if (kc + 1 > r1) s[ni][3] = -1e30f;
                mx0 = fmaxf(mx0, fmaxf(s[ni][0], s[ni][1]));
                mx1 = fmaxf(mx1, fmaxf(s[ni][2], s[ni][3]));
            }
            mx0 = fmaxf(mx0, __shfl_xor_sync(0xffffffffu, mx0, 1));
            mx0 = fmaxf(mx0, __shfl_xor_sync(0xffffffffu, mx0, 2));
            mx1 = fmaxf(mx1, __shfl_xor_sync(0xffffffffu, mx1, 1));
            mx1 = fmaxf(mx1, __shfl_xor_sync(0xffffffffu, mx1, 2));
            float nm0 = fmaxf(m0, mx0), nm1 = fmaxf(m1, mx1);
            float c0 = __expf(m0 - nm0), c1 = __expf(m1 - nm1);
            m0 = nm0; m1 = nm1;
            float p[8][4];
            float ls0 = 0.f, ls1 = 0.f;
            #pragma unroll
            for (int ni = 0; ni < 8; ni++) {
                p[ni][0] = __expf(s[ni][0] - nm0);
                p[ni][1] = __expf(s[ni][1] - nm0);
                p[ni][2] = __expf(s[ni][2] - nm1);
                p[ni][3] = __expf(s[ni][3] - nm1);
                ls0 += p[ni][0] + p[ni][1];
                ls1 += p[ni][2] + p[ni][3];
            }
            l0 = l0 * c0 + ls0;
            l1 = l1 * c1 + ls1;
            #pragma unroll
            for (int ni = 0; ni < 8; ni++) {
                o[ni][0] *= c0; o[ni][1] *= c0; o[ni][2] *= c1; o[ni][3] *= c1;
            }
            // ---- pack P as A-fragments (hi/lo) ----
            #pragma unroll
            for (int ss = 0; ss < 4; ss++) {
                pack_hl(p[2*ss][0],   p[2*ss][1],   ph[ss][0], pl[ss][0]);
                pack_hl(p[2*ss][2],   p[2*ss][3],   ph[ss][1], pl[ss][1]);
                pack_hl(p[2*ss+1][0], p[2*ss+1][1], ph[ss][2], pl[ss][2]);
                pack_hl(p[2*ss+1][2], p[2*ss+1][3], ph[ss][3], pl[ss][3]);
            }
        }
        __syncthreads();   // S-phase reads done
        {   // ---- stage V transposed [d][key] hi/lo ----
            int kk = tid >> 2, d0 = (tid & 3) * 16;
            const float* vp = qkv + base + (size_t)(j0 + kk) * C3 + 2 * CDIM + h * HD + d0;
            #pragma unroll
            for (int i = 0; i < 4; i++) {
                float4 v = ((const float4*)vp)[i];
                int d = d0 + i * 4;
                uint16_t hh, ll;
                bsplit(v.x, hh, ll);
                sH[(d + 0) * ST + kk] = __ushort_as_bfloat16(hh);
                sL[(d + 0) * ST + kk] = __ushort_as_bfloat16(ll);
                bsplit(v.y, hh, ll);
                sH[(d + 1) * ST + kk] = __ushort_as_bfloat16(hh);
                sL[(d + 1) * ST + kk] = __ushort_as_bfloat16(ll);
                bsplit(v.z, hh, ll);
                sH[(d + 2) * ST + kk] = __ushort_as_bfloat16(hh);
                sL[(d + 2) * ST + kk] = __ushort_as_bfloat16(ll);
                bsplit(v.w, hh, ll);
                sH[(d + 3) * ST + kk] = __ushort_as_bfloat16(hh);
                sL[(d + 3) * ST + kk] = __ushort_as_bfloat16(ll);
            }
        }
        __syncthreads();
        if (act) {
            // ---- O += P @ V : n-tiles are dim groups, k-steps over keys ----
            #pragma unroll
            for (int ni = 0; ni < 8; ni++)
                #pragma unroll
                for (int ss = 0; ss < 4; ss++) {
                    int ib = (8 * ni + g) * ST + 16 * ss + 2 * tg;
                    uint32_t bh[2] = { *(const uint32_t*)&sH[ib], *(const uint32_t*)&sH[ib + 8] };
                    uint32_t bl[2] = { *(const uint32_t*)&sL[ib], *(const uint32_t*)&sL[ib + 8] };
                    mma_bf16(o[ni], ph[ss], bh);
                    mma_bf16(o[ni], ph[ss], bl);
                    mma_bf16(o[ni], pl[ss], bh);
                }
        }
    }

    // ---- epilogue ----
    l0 += __shfl_xor_sync(0xffffffffu, l0, 1);
    l0 += __shfl_xor_sync(0xffffffffu, l0, 2);
    l1 += __shfl_xor_sync(0xffffffffu, l1, 1);
    l1 += __shfl_xor_sync(0xffffffffu, l1, 2);
    float i0 = 1.f / l0, i1 = 1.f / l1;
    float* o0 = att + (size_t)(b * TSEQ + qw0 + g) * CDIM + h * HD;
    float* o1 = o0 + 8 * CDIM;
    #pragma unroll
    for (int ni = 0; ni < 8; ni++) {
        float2 a; a.x = o[ni][0] * i0; a.y = o[ni][1] * i0;
        float2 c; c.x = o[ni][2] * i1; c.y = o[ni][3] * i1;
        *(float2*)(o0 + 8 * ni + 2 * tg) = a;
        *(float2*)(o1 + 8 * ni + 2 * tg) = c;
    }
}

// ---------------- per-row cross-entropy ----------------
__global__ __launch_bounds__(256) void loss_row_kernel(const float* __restrict__ logits,
                                                       const int* __restrict__ targets) {
    int row = blockIdx.x;
    const float* x = logits + (size_t)row * VOCAB;
    __shared__ float sh[8];
    float mx = -1e30f;
    for (int c = threadIdx.x; c < VOCAB; c += 256) mx = fmaxf(mx, x[c]);
    #pragma unroll
    for (int o = 16; o; o >>= 1) mx = fmaxf(mx, __shfl_down_sync(0xffffffffu, mx, o));
    if ((threadIdx.x & 31) == 0) sh[threadIdx.x >> 5] = mx;
    __syncthreads();
    if (threadIdx.x == 0) {
        float a = sh[0];
        #pragma unroll
        for (int i = 1; i < 8; i++) a = fmaxf(a, sh[i]);
        sh[0] = a;
    }
    __syncthreads();
    mx = sh[0];
    __syncthreads();
    float s = 0.f;
    for (int c = threadIdx.x; c < VOCAB; c += 256) s += expf(x[c] - mx);
    #pragma unroll
    for (int o = 16; o; o >>= 1) s += __shfl_down_sync(0xffffffffu, s, o);
    if ((threadIdx.x & 31) == 0) sh[threadIdx.x >> 5] = s;
    __syncthreads();
    if (threadIdx.x == 0) {
        float a = 0.f;
        #pragma unroll
        for (int i = 0; i < 8; i++) a += sh[i];
        g_rowloss[row] = (mx + logf(a)) - x[targets[row]];
    }
}

__global__ __launch_bounds__(1024) void loss_reduce_kernel(float* __restrict__ out) {
    __shared__ float sh[1024];
    int t = threadIdx.x;
    float s = 0.f;
    for (int i = t; i < NTOK; i += 1024) s += g_rowloss[i];
    sh[t] = s;
    __syncthreads();
    for (int o = 512; o; o >>= 1) {
        if (t < o) sh[t] += sh[t + o];
        __syncthreads();
    }
    if (t == 0) out[0] = sh[0] * (1.f / NTOK);
}

// ---------------- launch ----------------
extern "C" void kernel_launch(void* const* d_in, const int* in_sizes, int n_in,
                              void* d_out, int out_size) {
    const int*   x       = (const int*)  d_in[0];
    const int*   targets = (const int*)  d_in[1];
    const float* wte     = (const float*)d_in[2];
    const float* wpe     = (const float*)d_in[3];
    const float* ln1_w   = (const float*)d_in[4];
    const float* ln1_b   = (const float*)d_in[5];
    const float* attn_w  = (const float*)d_in[6];
    const float* attn_b  = (const float*)d_in[7];
    const float* proj_w  = (const float*)d_in[8];
    const float* proj_b  = (const float*)d_in[9];
    const float* ln2_w   = (const float*)d_in[10];
    const float* ln2_b   = (const float*)d_in[11];
    const float* fc_w    = (const float*)d_in[12];
    const float* fc_b    = (const float*)d_in[13];
    const float* fc2_w   = (const float*)d_in[14];
    const float* fc2_b   = (const float*)d_in[15];
    const float* lnf_w   = (const float*)d_in[16];
    const float* lnf_b   = (const float*)d_in[17];

    float* logits = (float*)d_out;
    float* lossp  = (float*)d_out + (out_size - 1);

    float *p_h, *p_hn, *p_qkv, *p_att, *p_fc;
    cudaGetSymbolAddress((void**)&p_h,   g_h);
    cudaGetSymbolAddress((void**)&p_hn,  g_hn);
    cudaGetSymbolAddress((void**)&p_qkv, g_qkv);
    cudaGetSymbolAddress((void**)&p_att, g_att);
    cudaGetSymbolAddress((void**)&p_fc,  g_fc);

    embed_kernel<<<NTOK, 256>>>(x, wte, wpe);

    for (int l = 0; l < NLAYER; l++) {
        ln_kernel<<<NTOK, 256>>>(p_h, ln1_w + (size_t)l * CDIM, ln1_b + (size_t)l * CDIM, p_hn);
        bf16_gemm<0, false><<<dim3(C3 / 128, NTOK / 128), 256>>>(
            p_hn, attn_w + (size_t)l * CDIM * C3, attn_b + (size_t)l * C3,
            nullptr, p_qkv, NTOK, C3, CDIM);
        attn_mma<<<dim3(TSEQ / 128, NHEAD, BATCH), 256>>>(p_qkv, p_att);
        bf16_gemm<2, false><<<dim3(CDIM / 128, NTOK / 128), 256>>>(
            p_att, proj_w + (size_t)l * CDIM * CDIM, proj_b + (size_t)l * CDIM,
            p_h, p_h, NTOK, CDIM, CDIM);
        ln_kernel<<<NTOK, 256>>>(p_h, ln2_w + (size_t)l * CDIM, ln2_b + (size_t)l * CDIM, p_hn);
        bf16_gemm<1, false><<<dim3(C4 / 128, NTOK / 128), 256>>>(
            p_hn, fc_w + (size_t)l * CDIM * C4, fc_b + (size_t)l * C4,
            nullptr, p_fc, NTOK, C4, CDIM);
        bf16_gemm<2, false><<<dim3(CDIM / 128, NTOK / 128), 256>>>(
            p_fc, fc2_w + (size_t)l * C4 * CDIM, fc2_b + (size_t)l * CDIM,
            p_h, p_h, NTOK, CDIM, C4);
    }

    ln_kernel<<<NTOK, 256>>>(p_h, lnf_w, lnf_b, p_hn);
    bf16_gemm<0, true><<<dim3(VOCAB / 128, NTOK / 128), 256>>>(
        p_hn, wte, nullptr, nullptr, logits, NTOK, VOCAB, CDIM);

    loss_row_kernel<<<NTOK, 256>>>(logits, targets);
    loss_reduce_kernel<<<1, 1024>>>(lossp);
}